// round 8
// baseline (speedup 1.0000x reference)
#include <cuda_runtime.h>

#define BATCH 128
#define NSTEP 16
#define DMC 0.95122942450071400910f   // exp(-1/20)
#define DSC 0.81873075307798185867f   // exp(-1/5)
#define NT 896

// um/us interleaved: float4 = (um_a, us_a, um_b, us_b) for neuron pair
__device__ float4 g_s1v[BATCH*12544];   // L1: 25088 neurons / 2
__device__ float4 g_s2v[BATCH*6272];    // L2: 12544 neurons / 2
__device__ float  g_wt1[3136*600];      // transposed w_fc1 [i][j]
__device__ unsigned long long g_bc[BATCH*8];

// ---------------- shared memory layout (bytes) ----------------
#define O_W1    0         // 800 f        -> 3200
#define O_WF2   3200      // 6000 f       -> 27200
#define O_ST1   27200     // 25088 u8     -> 52288  (alive: 0x80|tc ; dead: lat)
#define O_ST2   52288     // 12544 u8     -> 64832
#define O_SPK1  64832     // 896 u32      -> 68416
#define O_SPK2  68416     // 896 u32      -> 72000
#define O_ENCB  72000     // 784 u8       -> 72784
#define O_ENCN  72784     // 28 i32       -> 72896
#define O_B1N   72896     // 14 i32(pad)  -> 72960
#define O_B1    72960     // 14*448 u16   -> 85504
#define O_PM    85504     // 98 u32(pad)  -> 85904
#define O_PC    85904     // 98 i32(pad)  -> 86304
#define O_LIST  86304     // 3136 u16     -> 92576
#define O_N     92576     // i32 (pad)    -> 92592
#define O_F1S   92592     // 600 u8(pad)  -> 93200
#define O_UMF1  93200     // 600 f        -> 95600
#define O_USF1  95600     // 600 f        -> 98000
#define O_SAVF1 98000     // 600 u8(pad)  -> 98608
#define O_UMF2  98608     // 10 f         -> 98648
#define O_USF2  98648     // 10 f         -> 98688
#define O_TEL   98688     // 10 f         -> 98728
#define O_OUTT  98728     // 10 f         -> 98768
#define O_OUTU  98768     // 10 f         -> 98808
#define O_SAVF2 98808     // 10 u8 (pad)  -> 98824
#define O_CNT   98824     // 6 i32        -> 98848
#define O_BIG   98848     // 28672 f      -> 213536 (conv2 acc aliases low part)
#define SMEM_TOTAL 213536

__global__ void k_transpose(const float* __restrict__ w) {
    __shared__ float tile[32][33];
    int i0 = blockIdx.x * 32, j0 = blockIdx.y * 32;
    int tx = threadIdx.x, ty = threadIdx.y;
    #pragma unroll
    for (int r = 0; r < 4; r++) {
        int j = j0 + ty + r * 8, i = i0 + tx;
        if (j < 600 && i < 3136) tile[ty + r * 8][tx] = w[j * 3136 + i];
    }
    __syncthreads();
    #pragma unroll
    for (int r = 0; r < 4; r++) {
        int i = i0 + ty + r * 8, j = j0 + tx;
        if (i < 3136 && j < 600) g_wt1[i * 600 + j] = tile[tx][ty + r * 8];
    }
}

// alive-neuron update; st byte: 0x80|tc alive (tc = firstActiveStep+1, 0 = um never nonzero)
__device__ __forceinline__ int upd_neuron(float& um_, float& us_, float acc,
                                          unsigned char* stp, int s) {
    float um = um_ * DMC + acc;
    float us = us_ * DSC + acc;
    um_ = um; us_ = us;
    int tc = *stp & 0x1F;
    if (tc == 0 && um != 0.f) tc = s + 1;
    float u = um - us;
    if (u - 1.f > 0.f) {
        int te = tc ? (s - tc + 2) : 0;
        *stp = (unsigned char)(te + 1);        // dead: lat
        return 1;
    }
    *stp = (unsigned char)(0x80 | tc);
    return 0;
}

__global__ void __launch_bounds__(NT, 1) k_fused(
    const float* __restrict__ input, const float* __restrict__ w1g,
    const float* __restrict__ w2, const float* __restrict__ wf2g,
    float* __restrict__ out)
{
    extern __shared__ char sm[];
    float*          s_w1   = (float*)(sm + O_W1);
    float*          s_wf2  = (float*)(sm + O_WF2);
    unsigned char*  s_st1  = (unsigned char*)(sm + O_ST1);
    unsigned char*  s_st2  = (unsigned char*)(sm + O_ST2);
    unsigned*       s_spk1 = (unsigned*)(sm + O_SPK1);
    unsigned*       s_spk2 = (unsigned*)(sm + O_SPK2);
    unsigned char*  s_encb = (unsigned char*)(sm + O_ENCB);
    int*            s_encn = (int*)(sm + O_ENCN);
    int*            s_b1n  = (int*)(sm + O_B1N);
    unsigned short* s_b1   = (unsigned short*)(sm + O_B1);
    unsigned*       s_pm   = (unsigned*)(sm + O_PM);
    int*            s_pc   = (int*)(sm + O_PC);
    unsigned short* s_list = (unsigned short*)(sm + O_LIST);
    int*            s_n    = (int*)(sm + O_N);
    unsigned char*  s_f1s  = (unsigned char*)(sm + O_F1S);
    float*          s_umf1 = (float*)(sm + O_UMF1);
    float*          s_usf1 = (float*)(sm + O_USF1);
    unsigned char*  s_savf1= (unsigned char*)(sm + O_SAVF1);
    float*          s_umf2 = (float*)(sm + O_UMF2);
    float*          s_usf2 = (float*)(sm + O_USF2);
    float*          s_tel  = (float*)(sm + O_TEL);
    float*          s_outt = (float*)(sm + O_OUTT);
    float*          s_outu = (float*)(sm + O_OUTU);
    unsigned char*  s_savf2= (unsigned char*)(sm + O_SAVF2);
    int*            s_cnt  = (int*)(sm + O_CNT);
    float*          s_big  = (float*)(sm + O_BIG);

    int b = blockIdx.x, t = threadIdx.x;
    int w = t >> 5, lane = t & 31;
    int o1 = t / 28, rr1 = t % 28;       // L1 row owner
    int o2 = t / 14, rr2 = t % 14;       // L2 row owner

    // ----------------------------- init --------------------------------------
    {
        unsigned* p1 = (unsigned*)s_st1;
        for (int i = t; i < 6272; i += NT) p1[i] = 0x80808080u;
        unsigned* p2 = (unsigned*)s_st2;
        for (int i = t; i < 3136; i += NT) p2[i] = 0x80808080u;
    }
    for (int i = t; i < 28672; i += NT) s_big[i] = 0.f;
    for (int i = t; i < 6000; i += NT) s_wf2[i] = wf2g[i];
    if (t < 800) s_w1[t] = w1g[t];
    if (t < 600) { s_umf1[t] = 0.f; s_usf1[t] = 0.f; s_savf1[t] = 1; }
    if (t < 10) { s_umf2[t] = 0.f; s_usf2[t] = 0.f; s_tel[t] = 0.f;
                  s_outt[t] = 16.f; s_outu[t] = 0.f; s_savf2[t] = 1; }
    if (t < 6) s_cnt[t] = 0;

    float r_x = 0.f, r_encu = 0.f;
    if (lane < 28) r_x = input[b * 784 + w * 28 + lane] * 0.3f;

    unsigned aliveM1 = 0x0FFFFFFFu, needU1 = 0u;
    unsigned aliveM2 = 0x3FFFu,     needU2 = 0u;
    bool dirty1 = false, dirty2 = false;
    int c0 = 0, c1 = 0, c2 = 0, c3 = 0, c4 = 0;
    __syncthreads();

    for (int s = 0; s < NSTEP; s++) {
        // ---- A: encoder (warp w = input row w) + bucket1 (warp-local) ----
        {
            int spk = 0;
            if (lane < 28) {
                float u = r_encu;
                float notspk = (u > 1.f) ? 0.f : 1.f;
                u = u * DMC * notspk + r_x;
                r_encu = u;
                spk = (u > 1.f) ? 1 : 0;
                c0 += spk;
            }
            unsigned m = __ballot_sync(0xffffffffu, spk);
            if (spk) s_encb[w * 28 + __popc(m & ((1u << lane) - 1u))] =
                         (unsigned char)lane;
            if (lane == 0) s_encn[w] = __popc(m);
        }
        __syncthreads();

        // ---- B: conv1 scatter + L1 update (own row) ----
        if (aliveM1) {
            float* row = s_big + t * 32;
            bool touched = false;
            #pragma unroll
            for (int dy = -2; dy <= 2; dy++) {
                int y = rr1 + dy;
                if ((unsigned)y >= 28u) continue;
                int nb = s_encn[y];
                if (!nb) continue;
                touched = true;
                const float* wr = s_w1 + o1 * 25 + (dy + 2) * 5;
                float w0 = wr[0], w1v = wr[1], w2v = wr[2], w3 = wr[3], w4 = wr[4];
                const unsigned char* bk = s_encb + y * 28;
                for (int q = 0; q < nb; q++) {
                    float* rp = row + bk[q];
                    rp[4] += w0; rp[3] += w1v; rp[2] += w2v; rp[1] += w3; rp[0] += w4;
                }
            }
            if (touched) dirty1 = true;
            unsigned spkm = 0;
            float4* gs = g_s1v + b * 12544 + t * 14;
            unsigned char* str = s_st1 + t * 28;
            #pragma unroll 2
            for (int p = 0; p < 14; p++) {
                int cb = 2 * p;
                float a0 = touched ? row[cb + 2] : 0.f;
                float a1 = touched ? row[cb + 3] : 0.f;
                bool need0 = ((aliveM1 >> cb) & 1) && (((needU1 >> cb) & 1) || a0 != 0.f);
                bool need1 = ((aliveM1 >> (cb+1)) & 1) && (((needU1 >> (cb+1)) & 1) || a1 != 0.f);
                if (!need0 && !need1) continue;
                float4 v = gs[p];
                // first touch THIS LAUNCH -> state must start at 0 (graph replay
                // leaves stale values in global memory)
                if (!((needU1 >> cb) & 1))       { v.x = 0.f; v.y = 0.f; }
                if (!((needU1 >> (cb + 1)) & 1)) { v.z = 0.f; v.w = 0.f; }
                if (need0) {
                    needU1 |= 1u << cb;
                    if (upd_neuron(v.x, v.y, a0, str + cb, s)) {
                        spkm |= 1u << cb; aliveM1 &= ~(1u << cb); c1++;
                    }
                }
                if (need1) {
                    needU1 |= 1u << (cb+1);
                    if (upd_neuron(v.z, v.w, a1, str + cb + 1, s)) {
                        spkm |= 1u << (cb+1); aliveM1 &= ~(1u << (cb+1)); c1++;
                    }
                }
                gs[p] = v;
            }
            s_spk1[t] = spkm;
        } else s_spk1[t] = 0;
        __syncthreads();

        // ---- C: pool1 + bucket2 build (warps 0-13; warp w = pooled row w) ----
        if (w < 14) {
            int py = w, n = 0;
            for (int ci = 0; ci < 32; ci++) {
                int bit = 0;
                if (lane < 14) {
                    int t0 = ci * 28 + 2 * py;
                    unsigned m0 = s_spk1[t0], m1 = s_spk1[t0 + 1];
                    int base0 = t0 * 28 + 2 * lane;
                    unsigned char a = s_st1[base0],      bb = s_st1[base0 + 1];
                    unsigned char cc = s_st1[base0 + 28], d = s_st1[base0 + 29];
                    int la = (a & 0x80) ? 16 : a;
                    int lb = (bb & 0x80) ? 16 : bb;
                    int lc = (cc & 0x80) ? 16 : cc;
                    int ld = (d & 0x80) ? 16 : d;
                    int lm = min(min(la, lb), min(lc, ld));
                    int sa = (m0 >> (2 * lane)) & 1, sb = (m0 >> (2 * lane + 1)) & 1;
                    int sc = (m1 >> (2 * lane)) & 1, sd = (m1 >> (2 * lane + 1)) & 1;
                    bit = (sa && la == lm) || (sb && lb == lm) ||
                          (sc && lc == lm) || (sd && ld == lm);
                }
                unsigned m = __ballot_sync(0xffffffffu, bit);
                if (bit) s_b1[py * 448 + n + __popc(m & ((1u << lane) - 1u))] =
                             (unsigned short)((ci << 4) | lane);
                n += __popc(m);
            }
            if (lane == 0) s_b1n[py] = n;
        }
        __syncthreads();

        // ---- D: conv2 scatter (weight-prefetch pipeline) + L2 update ----
        if (aliveM2) {
            float* row = s_big + t * 18;
            bool touched = false;
            #pragma unroll
            for (int dy = -2; dy <= 2; dy++) {
                int y = rr2 + dy;
                if ((unsigned)y >= 14u) continue;
                int nb = s_b1n[y];
                if (!nb) continue;
                touched = true;
                const unsigned short* bk = s_b1 + y * 448;
                const float* wb = w2 + o2 * 800 + (dy + 2) * 5;
                int q = 0;
                int ci = bk[0] >> 4;
                const float* wr = wb + ci * 25;
                float w0 = __ldg(wr), w1v = __ldg(wr+1), w2v = __ldg(wr+2),
                      w3 = __ldg(wr+3), w4 = __ldg(wr+4);
                while (q < nb) {
                    int qn = q + 1;
                    while (qn < nb && (bk[qn] >> 4) == ci) qn++;
                    int ciN = 0;
                    float n0 = 0.f, n1 = 0.f, n2 = 0.f, n3 = 0.f, n4 = 0.f;
                    bool more = qn < nb;
                    if (more) {
                        ciN = bk[qn] >> 4;
                        const float* nr = wb + ciN * 25;
                        n0 = __ldg(nr); n1 = __ldg(nr+1); n2 = __ldg(nr+2);
                        n3 = __ldg(nr+3); n4 = __ldg(nr+4);
                    }
                    for (; q < qn; q++) {
                        float* rp = row + (bk[q] & 15);
                        rp[4] += w0; rp[3] += w1v; rp[2] += w2v; rp[1] += w3; rp[0] += w4;
                    }
                    ci = ciN; w0 = n0; w1v = n1; w2v = n2; w3 = n3; w4 = n4;
                }
            }
            if (touched) dirty2 = true;
            unsigned spkm = 0;
            float4* gs = g_s2v + b * 6272 + t * 7;
            unsigned char* str = s_st2 + t * 14;
            #pragma unroll 2
            for (int p = 0; p < 7; p++) {
                int cb = 2 * p;
                float a0 = touched ? row[cb + 2] : 0.f;
                float a1 = touched ? row[cb + 3] : 0.f;
                bool need0 = ((aliveM2 >> cb) & 1) && (((needU2 >> cb) & 1) || a0 != 0.f);
                bool need1 = ((aliveM2 >> (cb+1)) & 1) && (((needU2 >> (cb+1)) & 1) || a1 != 0.f);
                if (!need0 && !need1) continue;
                float4 v = gs[p];
                if (!((needU2 >> cb) & 1))       { v.x = 0.f; v.y = 0.f; }
                if (!((needU2 >> (cb + 1)) & 1)) { v.z = 0.f; v.w = 0.f; }
                if (need0) {
                    needU2 |= 1u << cb;
                    if (upd_neuron(v.x, v.y, a0, str + cb, s)) {
                        spkm |= 1u << cb; aliveM2 &= ~(1u << cb); c2++;
                    }
                }
                if (need1) {
                    needU2 |= 1u << (cb+1);
                    if (upd_neuron(v.z, v.w, a1, str + cb + 1, s)) {
                        spkm |= 1u << (cb+1); aliveM2 &= ~(1u << (cb+1)); c2++;
                    }
                }
                gs[p] = v;
            }
            s_spk2[t] = spkm;
        } else s_spk2[t] = 0;
        __syncthreads();

        // ---- E: pool2 masks + popc (warps 0-13); zero dirty acc rows ----
        if (w < 14) {
            #pragma unroll
            for (int k = 0; k < 7; k++) {
                int g = w * 7 + k;
                int L = g * 32 + lane;
                int ci = L / 49, p = L % 49, py = p / 7, px = p % 7;
                int t0 = ci * 14 + 2 * py;
                unsigned m0 = s_spk2[t0], m1 = s_spk2[t0 + 1];
                int base0 = t0 * 14 + 2 * px;
                unsigned char a = s_st2[base0],      bb = s_st2[base0 + 1];
                unsigned char cc = s_st2[base0 + 14], d = s_st2[base0 + 15];
                int la = (a & 0x80) ? 16 : a;
                int lb = (bb & 0x80) ? 16 : bb;
                int lc = (cc & 0x80) ? 16 : cc;
                int ld = (d & 0x80) ? 16 : d;
                int lm = min(min(la, lb), min(lc, ld));
                int sa = (m0 >> (2 * px)) & 1, sb = (m0 >> (2 * px + 1)) & 1;
                int sc = (m1 >> (2 * px)) & 1, sd = (m1 >> (2 * px + 1)) & 1;
                int bit = (sa && la == lm) || (sb && lb == lm) ||
                          (sc && lc == lm) || (sd && ld == lm);
                unsigned m = __ballot_sync(0xffffffffu, bit);
                if (lane == 0) { s_pm[g] = m; s_pc[g] = __popc(m); }
            }
        }
        if (dirty1) {
            float* row = s_big + t * 32;
            #pragma unroll
            for (int i = 0; i < 32; i++) row[i] = 0.f;
            dirty1 = false;
        }
        if (dirty2) {
            float* row = s_big + t * 18;
            #pragma unroll
            for (int i = 0; i < 18; i++) row[i] = 0.f;
            dirty2 = false;
        }
        __syncthreads();

        // ---- F: prefix + expand active list (threads 0-97) ----
        if (t < 98) {
            int pre = 0;
            for (int g = 0; g < t; g++) pre += s_pc[g];
            unsigned m = s_pm[t];
            int k = 0;
            while (m) {
                int bit = __ffs(m) - 1; m &= m - 1;
                s_list[pre + k++] = (unsigned short)(t * 32 + bit);
            }
            if (t == 97) *s_n = pre + k;
        }
        __syncthreads();

        // ---- G: fc1 (alive-gated, batched gather) ----
        if (t < 600) {
            if (s_savf1[t]) {
                int n = *s_n;
                const float* wp = g_wt1 + t;
                float acc = 0.f;
                int q = 0;
                for (; q + 4 <= n; q += 4) {
                    int i0 = (int)s_list[q] * 600, i1 = (int)s_list[q+1] * 600;
                    int i2 = (int)s_list[q+2] * 600, i3 = (int)s_list[q+3] * 600;
                    float v0 = __ldg(wp + i0), v1 = __ldg(wp + i1);
                    float v2 = __ldg(wp + i2), v3 = __ldg(wp + i3);
                    acc += v0; acc += v1; acc += v2; acc += v3;
                }
                for (; q < n; q++) acc += __ldg(wp + (int)s_list[q] * 600);
                float um = s_umf1[t] * DMC + acc;
                float us = s_usf1[t] * DSC + acc;
                s_umf1[t] = um; s_usf1[t] = us;
                float u = um - us;
                int spk = (u - 1.f > 0.f) ? 1 : 0;
                if (spk) { s_savf1[t] = 0; c3++; }
                s_f1s[t] = (unsigned char)spk;
            } else s_f1s[t] = 0;
        }
        __syncthreads();

        // ---- H: fc2 + output neuron (warps 0-9) ----
        if (w < 10) {
            int alive = s_savf2[w];
            float acc = 0.f;
            if (alive) {
                for (int i = lane; i < 600; i += 32)
                    if (s_f1s[i]) acc += s_wf2[w * 600 + i];
                #pragma unroll
                for (int off = 16; off; off >>= 1)
                    acc += __shfl_xor_sync(0xffffffffu, acc, off);
            }
            if (lane == 0) {
                float u = 0.f;
                int spk = 0;
                if (alive) {
                    float um = s_umf2[w] * DMC + acc;
                    float us = s_usf2[w] * DSC + acc;
                    s_umf2[w] = um; s_usf2[w] = us;
                    u = um - us;
                    spk = (u - 1.f > 0.f) ? 1 : 0;
                    if (spk) s_savf2[w] = 0;
                }
                float tel = s_tel[w];
                float uflag = (u != 0.f) ? 1.f : 0.f;
                if (tel + uflag != 0.f) tel += 1.f;
                s_tel[w] = tel;
                if (spk) { s_outt[w] += (tel - 16.f); s_outu[w] += u; c4++; }
            }
        }
        __syncthreads();
    }

    // ---- finalize ----
    if (c0) atomicAdd(&s_cnt[0], c0);
    if (c1) atomicAdd(&s_cnt[1], c1);
    if (c2) atomicAdd(&s_cnt[2], c2);
    if (c3) atomicAdd(&s_cnt[3], c3);
    if (c4) atomicAdd(&s_cnt[4], c4);
    __syncthreads();
    if (t < 10) {
        out[b * 10 + t] = s_outt[t];
        out[1280 + b * 10 + t] = s_outu[t];
    }
    if (t < 5) g_bc[b * 8 + t] = (unsigned long long)s_cnt[t];
}

__global__ void k_pack(float* __restrict__ out) {
    int t = threadIdx.x;
    if (t < 5) {
        unsigned long long sum = 0;
        for (int b = 0; b < BATCH; b++) sum += g_bc[b * 8 + t];
        out[2560 + t] = (float)sum;
    }
}

// ------------------------------ launch --------------------------------------
extern "C" void kernel_launch(void* const* d_in, const int* in_sizes, int n_in,
                              void* d_out, int out_size) {
    const float *input = 0, *w1 = 0, *w2 = 0, *wf1 = 0, *wf2 = 0;
    for (int i = 0; i < n_in; i++) {
        long s = in_sizes[i];
        if (s == 100352 || s == 401408)        input = (const float*)d_in[i];
        else if (s == 800 || s == 3200)        w1    = (const float*)d_in[i];
        else if (s == 51200 || s == 204800)    w2    = (const float*)d_in[i];
        else if (s == 1881600 || s == 7526400) wf1   = (const float*)d_in[i];
        else if (s == 6000 || s == 24000)      wf2   = (const float*)d_in[i];
    }
    if (!input || !w1 || !w2 || !wf1 || !wf2) {
        const float* p[5] = {0, 0, 0, 0, 0};
        int k = 0;
        for (int i = 0; i < n_in && k < 5; i++)
            if (in_sizes[i] > 8) p[k++] = (const float*)d_in[i];
        if (k < 5)
            for (int i = 0; i < n_in && k < 5; i++) p[k++] = (const float*)d_in[i];
        input = p[0]; w1 = p[1]; w2 = p[2]; wf1 = p[3]; wf2 = p[4];
    }
    float* out = (float*)d_out;

    cudaFuncSetAttribute(k_fused, cudaFuncAttributeMaxDynamicSharedMemorySize,
                         SMEM_TOTAL);

    k_transpose<<<dim3(98, 19), dim3(32, 8)>>>(wf1);
    k_fused<<<BATCH, NT, SMEM_TOTAL>>>(input, w1, w2, wf2, out);
    k_pack<<<1, 32>>>(out);
}